// round 14
// baseline (speedup 1.0000x reference)
#include <cuda_runtime.h>
#include <cuda_fp16.h>

#define N_NODES 100000
#define DIM     64
#define NB      8192
#define KP      32
#define KN      100
#define INV255  (1.0f / 255.0f)
#define B_PER_BLK 8
#define NBATCH  34          // per warp: 4 pos + 13 neg, x2 sets
#define NSTG    4           // cp.async ring depth

// Scratch (__device__ globals; left zeroed after every execution -> deterministic).
__device__ unsigned g_Zq[N_NODES * 16];   // 6.4 MB, u8-quantized sigmoid(P), 64B/row
__device__ float    g_acc[3];             // [0]=sumsq deg, [1]=adj, [2]=deg_dist
__device__ unsigned g_count;              // finalize election counter

// ---------------------------------------------------------------------------
// Prep: sigmoid(P) -> u8 g_Zq (x255), plus degree-loss sum of squares.
__global__ void prep_kernel(const float* __restrict__ P,
                            const float* __restrict__ W,
                            const float* __restrict__ deg) {
    const int lane   = threadIdx.x & 31;
    const int warp   = (blockIdx.x * blockDim.x + threadIdx.x) >> 5;
    const int nwarps = (gridDim.x * blockDim.x) >> 5;
    const int sub    = lane >> 4;
    const int q      = lane & 15;

    const float4 w = *(const float4*)(W + q * 4);

    float acc = 0.0f;
    for (int pair = warp; pair < N_NODES / 2; pair += nwarps) {
        const int row = pair * 2 + sub;
        const float4 p = *(const float4*)(P + (size_t)row * DIM + q * 4);
        const float z0 = 1.0f / (1.0f + __expf(-p.x));
        const float z1 = 1.0f / (1.0f + __expf(-p.y));
        const float z2 = 1.0f / (1.0f + __expf(-p.z));
        const float z3 = 1.0f / (1.0f + __expf(-p.w));

        const unsigned packed =
              __float2uint_rn(z0 * 255.0f)
            | (__float2uint_rn(z1 * 255.0f) << 8)
            | (__float2uint_rn(z2 * 255.0f) << 16)
            | (__float2uint_rn(z3 * 255.0f) << 24);
        g_Zq[row * 16 + q] = packed;

        float s = z0 * w.x + z1 * w.y + z2 * w.z + z3 * w.w;
        #pragma unroll
        for (int o = 8; o; o >>= 1) s += __shfl_xor_sync(0xFFFFFFFFu, s, o);
        if (q == 0) {
            const float dd = s - deg[row];
            acc += dd * dd;
        }
    }

    #pragma unroll
    for (int o = 16; o; o >>= 1) acc += __shfl_xor_sync(0xFFFFFFFFu, acc, o);

    __shared__ float sh[32];
    if (lane == 0) sh[threadIdx.x >> 5] = acc;
    __syncthreads();
    if (threadIdx.x == 0) {
        float t = 0.0f;
        const int nw = blockDim.x >> 5;
        for (int i = 0; i < nw; i++) t += sh[i];
        atomicAdd(&g_acc[0], t);
    }
}

// ---------------------------------------------------------------------------
// SAD over this lane's 16 dims: 4x VABSDIFF4 + 4x IDP4A.
__device__ __forceinline__ unsigned sad16(uint4 r, uint4 zi, unsigned acc) {
    acc = __dp4a(__vabsdiffu4(zi.x, r.x), 0x01010101u, acc);
    acc = __dp4a(__vabsdiffu4(zi.y, r.y), 0x01010101u, acc);
    acc = __dp4a(__vabsdiffu4(zi.z, r.z), 0x01010101u, acc);
    acc = __dp4a(__vabsdiffu4(zi.w, r.w), 0x01010101u, acc);
    return acc;
}

// One warp per selected node b; 8 b's per block. Gathers flow through a
// 4-stage cp.async ring: each lane copies 16B of a row to SMEM and later
// reads back the SAME bytes (per-thread wait_group visibility, no sync).
// 34-batch unified schedule (pos0, neg0, pos1, neg1) keeps the pipe full.
__global__ __launch_bounds__(256) void contrast_kernel(
        const int* __restrict__ sel,
        const int* __restrict__ pos_adj,
        const int* __restrict__ neg_adj,
        const int* __restrict__ pos_deg,
        const int* __restrict__ neg_deg,
        float* __restrict__ out) {
    __shared__ unsigned s_idx[B_PER_BLK][NBATCH][8];   // byte offsets idx*64
    __shared__ uint4    s_stg[B_PER_BLK][NSTG][32];    // gather ring, 512B/stage

    const int tid  = threadIdx.x;
    const int warp = tid >> 5;
    const int lane = tid & 31;
    const int b    = blockIdx.x * B_PER_BLK + warp;
    const int g    = lane >> 2;           // group 0..7 (row within batch)
    const int gl   = lane & 3;            // 16B segment within 64B row

    // ---- stage this warp's index schedule ----
    {
        const int* pl[2] = { pos_adj, pos_deg };
        const int* nl[2] = { neg_adj, neg_deg };
        for (int i = lane; i < NBATCH * 8; i += 32) {
            const int t  = i >> 3;
            const int gg = i & 7;
            const int which = (t >= 17) ? 1 : 0;
            const int tt = t - which * 17;
            int idx;
            if (tt < 4) {
                idx = pl[which][b * KP + tt * 8 + gg];
            } else {
                int kb = (tt - 4) * 8 + gg;
                if (kb >= KN) kb = KN - 8;     // clamped; masked in compute
                idx = nl[which][b * KN + kb];
            }
            s_idx[warp][t][gg] = (unsigned)idx * 64u;
        }
    }
    __syncwarp();

    const uint4 zi = *(const uint4*)(g_Zq + sel[b] * 16 + gl * 4);

    const unsigned stg_base =
        (unsigned)__cvta_generic_to_shared(&s_stg[warp][0][0]);

    int ti = 0;   // issue counter
    #define ISSUE_ONE()                                                        \
        do {                                                                   \
            if (ti < NBATCH) {                                                 \
                const unsigned off = s_idx[warp][ti][g];                       \
                const char* src = (const char*)g_Zq + off + (gl << 4);         \
                const unsigned dst = stg_base + ((ti & (NSTG - 1)) << 9)       \
                                   + (lane << 4);                              \
                asm volatile("cp.async.cg.shared.global [%0], [%1], 16;"       \
                             :: "r"(dst), "l"(src) : "memory");                \
                ti++;                                                          \
            }                                                                  \
            asm volatile("cp.async.commit_group;" ::: "memory");               \
        } while (0)

    ISSUE_ONE(); ISSUE_ONE(); ISSUE_ONE();   // prologue: 3 in flight

    int tc = 0;   // compute counter
    float val[2];
    #pragma unroll
    for (int which = 0; which < 2; which++) {
        // ---- positives: 4 batches ----
        unsigned pos_acc = 0u;
        #pragma unroll
        for (int i = 0; i < 4; i++) {
            ISSUE_ONE();
            asm volatile("cp.async.wait_group 3;" ::: "memory");
            const uint4 r = s_stg[warp][tc & (NSTG - 1)][lane]; tc++;
            pos_acc = sad16(r, zi, pos_acc);
        }
        #pragma unroll
        for (int o = 16; o; o >>= 1)
            pos_acc += __shfl_xor_sync(0xFFFFFFFFu, pos_acc, o);

        // ---- negatives: 13 batches (last has 4 valid rows) ----
        float negsum = 0.0f;
        #pragma unroll
        for (int i = 0; i < 13; i++) {
            ISSUE_ONE();
            asm volatile("cp.async.wait_group 3;" ::: "memory");
            const uint4 r = s_stg[warp][tc & (NSTG - 1)][lane]; tc++;
            unsigned s = sad16(r, zi, 0u);
            s += __shfl_xor_sync(0xFFFFFFFFu, s, 1);
            s += __shfl_xor_sync(0xFFFFFFFFu, s, 2);
            if (i < 12 || g < 4)
                negsum += __expf(__uint2float_rn(s) * INV255);
        }
        negsum += __shfl_xor_sync(0xFFFFFFFFu, negsum, 4);
        negsum += __shfl_xor_sync(0xFFFFFFFFu, negsum, 8);
        negsum += __shfl_xor_sync(0xFFFFFFFFu, negsum, 16);

        val[which] = -__uint2float_rn(pos_acc) * (INV255 / KP) + __logf(negsum);
    }
    #undef ISSUE_ONE

    __shared__ float sh1[8], sh2[8];
    __shared__ bool  sh_last;
    if (lane == 0) {
        sh1[warp] = val[0];
        sh2[warp] = val[1];
    }
    __syncthreads();
    if (tid == 0) {
        float t1 = 0.0f, t2 = 0.0f;
        #pragma unroll
        for (int i = 0; i < 8; i++) { t1 += sh1[i]; t2 += sh2[i]; }
        atomicAdd(&g_acc[1], t1);
        atomicAdd(&g_acc[2], t2);
        __threadfence();
        sh_last = (atomicAdd(&g_count, 1u) == gridDim.x - 1);
    }
    __syncthreads();
    if (tid == 0 && sh_last) {
        const float a0 = *(volatile float*)&g_acc[0];
        const float a1 = *(volatile float*)&g_acc[1];
        const float a2 = *(volatile float*)&g_acc[2];
        out[0] = sqrtf(a0);
        out[1] = a1 * (1.0f / N_NODES);
        out[2] = a2 * (1.0f / N_NODES);
        g_acc[0] = 0.0f; g_acc[1] = 0.0f; g_acc[2] = 0.0f;
        g_count = 0u;
    }
}

// ---------------------------------------------------------------------------
extern "C" void kernel_launch(void* const* d_in, const int* in_sizes, int n_in,
                              void* d_out, int out_size) {
    const float* P   = (const float*)d_in[0];
    const float* W   = (const float*)d_in[1];
    const float* deg = (const float*)d_in[2];
    const int* sel   = (const int*)d_in[3];
    const int* pa    = (const int*)d_in[4];
    const int* na    = (const int*)d_in[5];
    const int* pd    = (const int*)d_in[6];
    const int* nd    = (const int*)d_in[7];
    float* out = (float*)d_out;

    prep_kernel<<<256, 1024>>>(P, W, deg);
    contrast_kernel<<<NB / B_PER_BLK, 256>>>(sel, pa, na, pd, nd, out);
}